// round 7
// baseline (speedup 1.0000x reference)
#include <cuda_runtime.h>
#include <math.h>

#define BATCH 64
#define SEQ   1024
#define ISZ   256
#define HSZ   512
#define GSZ   2048   /* 4*HSZ */
#define CON   768    /* ISZ+HSZ */
#define OSZ   256
#define NCTA  128
#define TPB   128

// ---------------- packed fp32x2 helpers (Blackwell sm_100+) ------------------
__device__ __forceinline__ void ffma2(unsigned long long& d,
                                      unsigned long long a,
                                      unsigned long long b) {
    asm("fma.rn.f32x2 %0, %1, %2, %0;" : "+l"(d) : "l"(a), "l"(b));
}
__device__ __forceinline__ unsigned long long pack2(float x, float y) {
    unsigned long long r;
    asm("mov.b64 %0, {%1, %2};" : "=l"(r) : "f"(x), "f"(y));
    return r;
}
__device__ __forceinline__ float2 unpack2(unsigned long long v) {
    float2 r;
    asm("mov.b64 {%0, %1}, %2;" : "=f"(r.x), "=f"(r.y) : "l"(v));
    return r;
}

// ---------------- device scratch (static globals: allocation-free) ----------
__device__ float    g_xg[(size_t)SEQ * BATCH * GSZ];   // x@Wx + bias, [t][b][2048]
__device__ float    g_Wall[CON * GSZ];                 // repacked [768,2048]
__device__ float    g_ball[GSZ];
__device__ float    g_h[2][HSZ * BATCH];               // ping-pong h^T  [k][b]
__device__ unsigned g_bar_count = 0;
__device__ unsigned g_bar_gen   = 0;

// ---------------- prep: repack weights, zero h ------------------------------
__global__ void prep_kernel(const float* __restrict__ Wf, const float* __restrict__ Wi,
                            const float* __restrict__ Wc, const float* __restrict__ Wo,
                            const float* __restrict__ bf, const float* __restrict__ bi,
                            const float* __restrict__ bc, const float* __restrict__ bo) {
    int idx = blockIdx.x * blockDim.x + threadIdx.x;
    int stride = gridDim.x * blockDim.x;
    for (int i = idx; i < CON * GSZ; i += stride) {
        int k = i >> 11; int n = i & (GSZ - 1);
        int g = n >> 9;  int j = n & (HSZ - 1);
        const float* W = (g == 0) ? Wf : (g == 1) ? Wi : (g == 2) ? Wc : Wo;
        g_Wall[i] = W[k * HSZ + j];
    }
    for (int i = idx; i < GSZ; i += stride) {
        int g = i >> 9; int j = i & (HSZ - 1);
        const float* bp = (g == 0) ? bf : (g == 1) ? bi : (g == 2) ? bc : bo;
        g_ball[i] = bp[j];
    }
    for (int i = idx; i < 2 * HSZ * BATCH; i += stride)
        ((float*)g_h)[i] = 0.f;
}

// ---------------- precompute xg = x @ Wx + b_all (packed FFMA2) -------------
// grid (16, 1024): blockIdx.x = n-tile (128 cols), blockIdx.y = timestep.
// CTA tile 64x128, K=256 in 16 chunks of 16; 256 thr, 4x8 micro-tile.
__global__ void __launch_bounds__(256) xgemm_kernel(const float* __restrict__ x) {
    __shared__ float As[16 * 68];    // [k][m] pad 68
    __shared__ float Bs[16 * 132];   // [k][n] pad 132
    int tid  = threadIdx.x;
    int n0   = blockIdx.x * 128;
    int tt   = blockIdx.y;
    int rowg = tid >> 4;             // 0..15 -> rows rowg*4..+3
    int colg = tid & 15;             // 0..15 -> cols colg*8..+7

    // packed accumulators: accP[r][p] holds cols (2p, 2p+1) for row r
    unsigned long long accP[4][4];
    #pragma unroll
    for (int p = 0; p < 4; p++) {
        unsigned long long bv = pack2(g_ball[n0 + colg * 8 + 2 * p],
                                      g_ball[n0 + colg * 8 + 2 * p + 1]);
        accP[0][p] = bv; accP[1][p] = bv; accP[2][p] = bv; accP[3][p] = bv;
    }

    int ar = tid >> 2, akq = tid & 3;
    const float* aptr = x + ((size_t)ar * SEQ + tt) * ISZ + akq * 4;

    #pragma unroll 1
    for (int ch = 0; ch < 16; ch++) {
        float4 av = *(const float4*)(aptr + ch * 16);
        float4 bv0, bv1;
        {
            int f = tid;       int bk = f >> 5, j4 = f & 31;
            bv0 = *(const float4*)&g_Wall[(ch * 16 + bk) * GSZ + n0 + j4 * 4];
            f = 256 + tid;     bk = f >> 5;     j4 = f & 31;
            bv1 = *(const float4*)&g_Wall[(ch * 16 + bk) * GSZ + n0 + j4 * 4];
        }
        __syncthreads();
        As[(akq * 4 + 0) * 68 + ar] = av.x;
        As[(akq * 4 + 1) * 68 + ar] = av.y;
        As[(akq * 4 + 2) * 68 + ar] = av.z;
        As[(akq * 4 + 3) * 68 + ar] = av.w;
        {
            int f = tid;       int bk = f >> 5, j4 = f & 31;
            *(float4*)&Bs[bk * 132 + j4 * 4] = bv0;
            f = 256 + tid;     bk = f >> 5;     j4 = f & 31;
            *(float4*)&Bs[bk * 132 + j4 * 4] = bv1;
        }
        __syncthreads();
        #pragma unroll
        for (int k = 0; k < 16; k++) {
            float4 a4 = *(const float4*)&As[k * 68 + rowg * 4];
            ulonglong2 b01 = *(const ulonglong2*)&Bs[k * 132 + colg * 8];
            ulonglong2 b23 = *(const ulonglong2*)&Bs[k * 132 + colg * 8 + 4];
            unsigned long long pa0 = pack2(a4.x, a4.x);
            unsigned long long pa1 = pack2(a4.y, a4.y);
            unsigned long long pa2 = pack2(a4.z, a4.z);
            unsigned long long pa3 = pack2(a4.w, a4.w);
            ffma2(accP[0][0], pa0, b01.x); ffma2(accP[0][1], pa0, b01.y);
            ffma2(accP[0][2], pa0, b23.x); ffma2(accP[0][3], pa0, b23.y);
            ffma2(accP[1][0], pa1, b01.x); ffma2(accP[1][1], pa1, b01.y);
            ffma2(accP[1][2], pa1, b23.x); ffma2(accP[1][3], pa1, b23.y);
            ffma2(accP[2][0], pa2, b01.x); ffma2(accP[2][1], pa2, b01.y);
            ffma2(accP[2][2], pa2, b23.x); ffma2(accP[2][3], pa2, b23.y);
            ffma2(accP[3][0], pa3, b01.x); ffma2(accP[3][1], pa3, b01.y);
            ffma2(accP[3][2], pa3, b23.x); ffma2(accP[3][3], pa3, b23.y);
        }
    }
    #pragma unroll
    for (int rr = 0; rr < 4; rr++) {
        size_t base = ((size_t)(tt * BATCH + rowg * 4 + rr)) * GSZ + n0 + colg * 8;
        *(ulonglong2*)&g_xg[base]     = make_ulonglong2(accP[rr][0], accP[rr][1]);
        *(ulonglong2*)&g_xg[base + 4] = make_ulonglong2(accP[rr][2], accP[rr][3]);
    }
}

// ---------------- persistent recurrent kernel -------------------------------
// 128 CTAs (one/SM), 128 thr. CTA ct owns hidden cols j0..j0+3 -> 16 gate cols
// [f0..3|i0..3|u0..3|o0..3]. W slice resident in smem, duplicated {w,w} pairs.
// h kept TRANSPOSED in global: g_h[buf][k*64 + b].
#define SM_WS2 0                       /* 512*32  = 16384 fl (dup pairs)      */
#define SM_HS0 16384                   /* 64*68   =  4352 fl                  */
#define SM_HS1 20736                   /* 64*68   =  4352 fl                  */
#define SM_XS  25088                   /* 64*16   =  1024 fl                  */
#define SM_GS  26112                   /* 64*16   =  1024 fl                  */
#define SM_HO  27136                   /* 4*64    =   256 fl                  */
#define SM_TOT 27392                   /* floats -> 109568 B                  */

__global__ void __launch_bounds__(TPB, 1) lstm_kernel() {
    extern __shared__ float sm[];
    float* Ws2 = sm + SM_WS2;
    float* Xs  = sm + SM_XS;
    float* Gs  = sm + SM_GS;
    float* Ho  = sm + SM_HO;
    float* HsB[2] = { sm + SM_HS0, sm + SM_HS1 };

    int tid = threadIdx.x;
    int ct  = blockIdx.x;
    int j0  = ct * 4;

    // resident W_h slice, duplicated: Ws2[k*32 + 2c + {0,1}] = W[k][c]
    for (int i = tid; i < HSZ * 16; i += TPB) {
        int k = i >> 4, c = i & 15, g = c >> 2, jj = c & 3;
        float w = g_Wall[(ISZ + k) * GSZ + g * HSZ + j0 + jj];
        Ws2[k * 32 + c * 2]     = w;
        Ws2[k * 32 + c * 2 + 1] = w;
    }

    int rowg = tid >> 3;        // 0..15 -> batch rows rowg*4..+3
    int colg = tid & 7;         // 0..7  -> cols 2*colg, 2*colg+1
    float c_reg0 = 0.f, c_reg1 = 0.f;   // cell state, register-resident
    __syncthreads();

    #pragma unroll 1
    for (int t = 0; t < SEQ; t++) {
        int rb = t & 1, wb = rb ^ 1;
        const float* hsrc = g_h[rb];

        // xg gate inputs for this step (independent of h): cooperative float4
        // idx in [0,256): b = idx>>2, g = idx&3 -> Xs[idx*4 .. +3]
        float4 xf0, xf1;
        {
            int i0 = tid, i1 = 128 + tid;
            size_t a0 = ((size_t)(t * BATCH + (i0 >> 2))) * GSZ + (i0 & 3) * HSZ + j0;
            size_t a1 = ((size_t)(t * BATCH + (i1 >> 2))) * GSZ + (i1 & 3) * HSZ + j0;
            xf0 = __ldg((const float4*)&g_xg[a0]);
            xf1 = __ldg((const float4*)&g_xg[a1]);
        }

        float4 pre[8];
        #define LOADCH(c)                                                        \
            _Pragma("unroll")                                                    \
            for (int q = 0; q < 8; q++)                                          \
                pre[q] = __ldcg((const float4*)&hsrc[(c) * 4096 + (q * 128 + tid) * 4]);
        #define STORECH(bufp)                                                    \
            _Pragma("unroll")                                                    \
            for (int q = 0; q < 8; q++) {                                        \
                int f = q * 128 + tid;                                           \
                *(float4*)&(bufp)[(f >> 4) * 68 + (f & 15) * 4] = pre[q];        \
            }

        LOADCH(0)
        STORECH(HsB[0])
        LOADCH(1)
        *(float4*)&Xs[tid * 4]         = xf0;
        *(float4*)&Xs[(128 + tid) * 4] = xf1;
        __syncthreads();

        unsigned long long a00 = 0ull, a01 = 0ull, a10 = 0ull, a11 = 0ull;

        #pragma unroll 1
        for (int ch = 0; ch < 8; ch++) {
            if (ch < 7) { STORECH(HsB[(ch + 1) & 1]) }
            if (ch < 6) { LOADCH(ch + 2) }
            const float* HB = HsB[ch & 1];
            const float* WB = Ws2 + ch * 64 * 32 + colg * 4;
            #pragma unroll 16
            for (int k = 0; k < 64; k++) {
                ulonglong2 hp = *(const ulonglong2*)&HB[k * 68 + rowg * 4];
                ulonglong2 wv = *(const ulonglong2*)&WB[k * 32];
                ffma2(a00, hp.x, wv.x); ffma2(a01, hp.x, wv.y);
                ffma2(a10, hp.y, wv.x); ffma2(a11, hp.y, wv.y);
            }
            __syncthreads();
        }
        #undef LOADCH
        #undef STORECH

        // scatter gate partials to [b][c] layout
        {
            float2 v;
            int c0 = colg * 2, r0 = rowg * 4;
            v = unpack2(a00); Gs[(r0 + 0) * 16 + c0]     = v.x; Gs[(r0 + 1) * 16 + c0]     = v.y;
            v = unpack2(a01); Gs[(r0 + 0) * 16 + c0 + 1] = v.x; Gs[(r0 + 1) * 16 + c0 + 1] = v.y;
            v = unpack2(a10); Gs[(r0 + 2) * 16 + c0]     = v.x; Gs[(r0 + 3) * 16 + c0]     = v.y;
            v = unpack2(a11); Gs[(r0 + 2) * 16 + c0 + 1] = v.x; Gs[(r0 + 3) * 16 + c0 + 1] = v.y;
        }
        __syncthreads();

        // gates + state update: thread handles cells p = 2*tid, 2*tid+1
        #pragma unroll
        for (int s = 0; s < 2; s++) {
            int p = tid * 2 + s; int b = p >> 2; int jj = p & 3;
            float gf = Gs[b * 16 + jj]      + Xs[b * 16 + jj];
            float gi = Gs[b * 16 + 4 + jj]  + Xs[b * 16 + 4 + jj];
            float gu = Gs[b * 16 + 8 + jj]  + Xs[b * 16 + 8 + jj];
            float go = Gs[b * 16 + 12 + jj] + Xs[b * 16 + 12 + jj];
            float fg = 1.f / (1.f + expf(-gf));
            float ig = 1.f / (1.f + expf(-gi));
            float ug = tanhf(gu);
            float og = 1.f / (1.f + expf(-go));
            float cold = s ? c_reg1 : c_reg0;
            float cn = fg * cold + ig * ug;
            if (s) c_reg1 = cn; else c_reg0 = cn;
            Ho[jj * 64 + b] = og * tanhf(cn);   // [jj][b] for coalesced h^T write
        }
        __syncthreads();

        // h^T writeback: rows j0..j0+3 = 256 contiguous floats
        g_h[wb][j0 * 64 + tid]       = Ho[tid];
        g_h[wb][j0 * 64 + 128 + tid] = Ho[128 + tid];

        // grid barrier (sense via monotonic generation: graph-replay safe)
        __threadfence();
        __syncthreads();
        if (tid == 0) {
            unsigned gen = *(volatile unsigned*)&g_bar_gen;
            unsigned ticket = atomicAdd(&g_bar_count, 1u);
            if (ticket == NCTA - 1) {
                g_bar_count = 0;
                __threadfence();
                atomicAdd(&g_bar_gen, 1u);
            } else {
                while (*(volatile unsigned*)&g_bar_gen == gen) { __nanosleep(64); }
            }
            __threadfence();
        }
        __syncthreads();
    }
}

// ---------------- final projection out = h_final @ W_out + b_out ------------
__global__ void __launch_bounds__(256) out_kernel(const float* __restrict__ Wout,
                                                  const float* __restrict__ bout,
                                                  float* __restrict__ out) {
    __shared__ float hs[HSZ];
    int b = blockIdx.x, n = threadIdx.x;
    for (int i = n; i < HSZ; i += 256) hs[i] = g_h[0][i * 64 + b];  // h^T
    __syncthreads();
    float acc = bout[n];
    #pragma unroll 8
    for (int k = 0; k < HSZ; k++) acc += hs[k] * Wout[k * OSZ + n];
    out[b * OSZ + n] = acc;
}

// ---------------- launch -----------------------------------------------------
extern "C" void kernel_launch(void* const* d_in, const int* in_sizes, int n_in,
                              void* d_out, int out_size) {
    const float* x    = (const float*)d_in[0];
    const float* Wf   = (const float*)d_in[1];
    const float* bf   = (const float*)d_in[2];
    const float* Wi   = (const float*)d_in[3];
    const float* bi   = (const float*)d_in[4];
    const float* Wc   = (const float*)d_in[5];
    const float* bc   = (const float*)d_in[6];
    const float* Wo   = (const float*)d_in[7];
    const float* bo   = (const float*)d_in[8];
    const float* Wout = (const float*)d_in[9];
    const float* bout = (const float*)d_in[10];
    float* out = (float*)d_out;

    cudaFuncSetAttribute(lstm_kernel, cudaFuncAttributeMaxDynamicSharedMemorySize,
                         SM_TOT * 4);

    prep_kernel<<<512, 256>>>(Wf, Wi, Wc, Wo, bf, bi, bc, bo);
    dim3 g(16, SEQ);
    xgemm_kernel<<<g, 256>>>(x);
    lstm_kernel<<<NCTA, TPB, SM_TOT * 4>>>();
    out_kernel<<<BATCH, 256>>>(Wout, bout, out);
}

// round 8
// speedup vs baseline: 1.0857x; 1.0857x over previous
#include <cuda_runtime.h>
#include <math.h>

#define BATCH 64
#define SEQ   1024
#define ISZ   256
#define HSZ   512
#define GSZ   2048   /* 4*HSZ */
#define CON   768    /* ISZ+HSZ */
#define OSZ   256
#define NCTA  128
#define TPB   256

// ---------------- device scratch (static globals: allocation-free) ----------
__device__ float    g_xg[(size_t)SEQ * BATCH * GSZ];   // x@Wx + bias, [t][b][2048]
__device__ float    g_Wall[CON * GSZ];                 // repacked [768,2048]
__device__ float    g_ball[GSZ];
__device__ float    g_h[2][HSZ * BATCH];               // ping-pong h^T  [k][b]
__device__ unsigned g_bar_count = 0;
__device__ unsigned g_bar_gen   = 0;

// ---------------- prep: repack weights, zero h ------------------------------
__global__ void prep_kernel(const float* __restrict__ Wf, const float* __restrict__ Wi,
                            const float* __restrict__ Wc, const float* __restrict__ Wo,
                            const float* __restrict__ bf, const float* __restrict__ bi,
                            const float* __restrict__ bc, const float* __restrict__ bo) {
    int idx = blockIdx.x * blockDim.x + threadIdx.x;
    int stride = gridDim.x * blockDim.x;
    for (int i = idx; i < CON * GSZ; i += stride) {
        int k = i >> 11; int n = i & (GSZ - 1);
        int g = n >> 9;  int j = n & (HSZ - 1);
        const float* W = (g == 0) ? Wf : (g == 1) ? Wi : (g == 2) ? Wc : Wo;
        g_Wall[i] = W[k * HSZ + j];
    }
    for (int i = idx; i < GSZ; i += stride) {
        int g = i >> 9; int j = i & (HSZ - 1);
        const float* bp = (g == 0) ? bf : (g == 1) ? bi : (g == 2) ? bc : bo;
        g_ball[i] = bp[j];
    }
    for (int i = idx; i < 2 * HSZ * BATCH; i += stride)
        ((float*)g_h)[i] = 0.f;
}

// ---------------- precompute xg = x @ Wx + b_all (plain FFMA, R1-proven) ----
// grid (16, 1024): blockIdx.x = n-tile (128 cols), blockIdx.y = timestep.
// CTA tile 64x128, K=256 in 16 chunks of 16; 256 thr, 4x8 micro-tile.
__global__ void __launch_bounds__(256) xgemm_kernel(const float* __restrict__ x) {
    __shared__ float As[16 * 68];    // [k][m] pad 68
    __shared__ float Bs[16 * 132];   // [k][n] pad 132
    int tid  = threadIdx.x;
    int n0   = blockIdx.x * 128;
    int tt   = blockIdx.y;
    int rowg = tid >> 4;             // 0..15 -> rows rowg*4..+3
    int colg = tid & 15;             // 0..15 -> cols colg*8..+7

    float acc[4][8];
    #pragma unroll
    for (int cc = 0; cc < 8; cc++) {
        float b = g_ball[n0 + colg * 8 + cc];
        acc[0][cc] = b; acc[1][cc] = b; acc[2][cc] = b; acc[3][cc] = b;
    }

    int ar = tid >> 2, akq = tid & 3;
    const float* aptr = x + ((size_t)ar * SEQ + tt) * ISZ + akq * 4;

    #pragma unroll 1
    for (int ch = 0; ch < 16; ch++) {
        float4 av = *(const float4*)(aptr + ch * 16);
        float4 bv0, bv1;
        {
            int f = tid;       int bk = f >> 5, j4 = f & 31;
            bv0 = *(const float4*)&g_Wall[(ch * 16 + bk) * GSZ + n0 + j4 * 4];
            f = 256 + tid;     bk = f >> 5;     j4 = f & 31;
            bv1 = *(const float4*)&g_Wall[(ch * 16 + bk) * GSZ + n0 + j4 * 4];
        }
        __syncthreads();
        As[(akq * 4 + 0) * 68 + ar] = av.x;
        As[(akq * 4 + 1) * 68 + ar] = av.y;
        As[(akq * 4 + 2) * 68 + ar] = av.z;
        As[(akq * 4 + 3) * 68 + ar] = av.w;
        {
            int f = tid;       int bk = f >> 5, j4 = f & 31;
            *(float4*)&Bs[bk * 132 + j4 * 4] = bv0;
            f = 256 + tid;     bk = f >> 5;     j4 = f & 31;
            *(float4*)&Bs[bk * 132 + j4 * 4] = bv1;
        }
        __syncthreads();
        #pragma unroll
        for (int k = 0; k < 16; k++) {
            float4 a4  = *(const float4*)&As[k * 68 + rowg * 4];
            float4 b40 = *(const float4*)&Bs[k * 132 + colg * 8];
            float4 b41 = *(const float4*)&Bs[k * 132 + colg * 8 + 4];
            float a[4]  = {a4.x, a4.y, a4.z, a4.w};
            float bb[8] = {b40.x, b40.y, b40.z, b40.w, b41.x, b41.y, b41.z, b41.w};
            #pragma unroll
            for (int rr = 0; rr < 4; rr++)
                #pragma unroll
                for (int cc = 0; cc < 8; cc++)
                    acc[rr][cc] += a[rr] * bb[cc];
        }
    }
    #pragma unroll
    for (int rr = 0; rr < 4; rr++) {
        size_t base = ((size_t)(tt * BATCH + rowg * 4 + rr)) * GSZ + n0 + colg * 8;
        *(float4*)&g_xg[base]     = make_float4(acc[rr][0], acc[rr][1], acc[rr][2], acc[rr][3]);
        *(float4*)&g_xg[base + 4] = make_float4(acc[rr][4], acc[rr][5], acc[rr][6], acc[rr][7]);
    }
}

// ---------------- persistent recurrent kernel -------------------------------
// 128 CTAs (one/SM), 256 thr (2 warps/SMSP for latency hiding). CTA ct owns
// hidden cols j0..j0+3 -> 16 gate cols [f|i|u|o]x4. Plain FFMA (rt2-proven).
// h kept TRANSPOSED in global: g_h[buf][k*64 + b]. Micro-tile 2b x 2c.
#define SM_WS  0                       /* 512*16 = 8192 fl                    */
#define SM_HS0 8192                    /* 64*68  = 4352 fl                    */
#define SM_HS1 12544                   /* 64*68  = 4352 fl                    */
#define SM_XS  16896                   /* 64*16  = 1024 fl                    */
#define SM_GS  17920                   /* 64*16  = 1024 fl                    */
#define SM_HO  18944                   /* 4*64   =  256 fl                    */
#define SM_TOT 19200                   /* floats -> 76800 B                   */

__global__ void __launch_bounds__(TPB, 1) lstm_kernel() {
    extern __shared__ float sm[];
    float* Ws = sm + SM_WS;
    float* Xs = sm + SM_XS;
    float* Gs = sm + SM_GS;
    float* Ho = sm + SM_HO;
    float* HsB[2] = { sm + SM_HS0, sm + SM_HS1 };

    int tid = threadIdx.x;
    int ct  = blockIdx.x;
    int j0  = ct * 4;

    // resident W_h slice: Ws[k*16 + c], c = gate*4 + jj
    for (int i = tid; i < HSZ * 16; i += TPB) {
        int k = i >> 4, c = i & 15, g = c >> 2, jj = c & 3;
        Ws[i] = g_Wall[(ISZ + k) * GSZ + g * HSZ + j0 + jj];
    }

    int rowg = tid >> 3;        // 0..31 -> batch rows rowg*2, rowg*2+1
    int colg = tid & 7;         // 0..7  -> cols colg*2, colg*2+1
    int b0   = rowg * 2;
    int c0   = colg * 2;
    float c_reg = 0.f;          // this thread's single cell (p = tid)
    __syncthreads();

    #pragma unroll 1
    for (int t = 0; t < SEQ; t++) {
        int rb = t & 1, wb = rb ^ 1;
        const float* hsrc = g_h[rb];

        // xg gate inputs (independent of h): 1 coalesced-ish float4 / thread
        // tid -> b = tid>>2, g = tid&3; dest Xs[tid*4] == Xs[b*16 + g*4]
        float4 xf = __ldg((const float4*)
            &g_xg[((size_t)(t * BATCH + (tid >> 2))) * GSZ + (tid & 3) * HSZ + j0]);

        float4 pre[4];
        #define LOADCH(c)                                                        \
            _Pragma("unroll")                                                    \
            for (int q = 0; q < 4; q++)                                          \
                pre[q] = __ldcg((const float4*)&hsrc[(c) * 4096 + (q * 256 + tid) * 4]);
        #define STORECH(bufp)                                                    \
            _Pragma("unroll")                                                    \
            for (int q = 0; q < 4; q++) {                                        \
                int f = q * 256 + tid;                                           \
                *(float4*)&(bufp)[(f >> 4) * 68 + (f & 15) * 4] = pre[q];        \
            }

        LOADCH(0)
        STORECH(HsB[0])
        LOADCH(1)
        *(float4*)&Xs[tid * 4] = xf;
        __syncthreads();

        float a00 = 0.f, a01 = 0.f, a10 = 0.f, a11 = 0.f;

        #pragma unroll 1
        for (int ch = 0; ch < 8; ch++) {
            if (ch < 7) { STORECH(HsB[(ch + 1) & 1]) }
            if (ch < 6) { LOADCH(ch + 2) }
            const float* HB = HsB[ch & 1];
            const float* Wp = Ws + ch * 64 * 16;
            #pragma unroll 16
            for (int k = 0; k < 64; k++) {
                float2 hv = *(const float2*)&HB[k * 68 + b0];
                float2 wv = *(const float2*)&Wp[k * 16 + c0];
                a00 += hv.x * wv.x; a01 += hv.x * wv.y;
                a10 += hv.y * wv.x; a11 += hv.y * wv.y;
            }
            __syncthreads();
        }
        #undef LOADCH
        #undef STORECH

        // scatter gate partials to [b][c] layout
        Gs[(b0 + 0) * 16 + c0]     = a00;
        Gs[(b0 + 0) * 16 + c0 + 1] = a01;
        Gs[(b0 + 1) * 16 + c0]     = a10;
        Gs[(b0 + 1) * 16 + c0 + 1] = a11;
        __syncthreads();

        // gates + state update: thread handles cell p = tid
        {
            int p = tid; int b = p >> 2; int jj = p & 3;
            float gf = Gs[b * 16 + jj]      + Xs[b * 16 + jj];
            float gi = Gs[b * 16 + 4 + jj]  + Xs[b * 16 + 4 + jj];
            float gu = Gs[b * 16 + 8 + jj]  + Xs[b * 16 + 8 + jj];
            float go = Gs[b * 16 + 12 + jj] + Xs[b * 16 + 12 + jj];
            float fg = 1.f / (1.f + expf(-gf));
            float ig = 1.f / (1.f + expf(-gi));
            float ug = tanhf(gu);
            float og = 1.f / (1.f + expf(-go));
            float cn = fg * c_reg + ig * ug;
            c_reg = cn;
            Ho[jj * 64 + b] = og * tanhf(cn);   // [jj][b] for coalesced h^T write
        }
        __syncthreads();

        // h^T writeback: rows j0..j0+3 = 256 contiguous floats, 1 store/thread
        g_h[wb][j0 * 64 + tid] = Ho[tid];

        // grid barrier (sense via monotonic generation: graph-replay safe,
        // pure spin — exact R1-proven form)
        __threadfence();
        __syncthreads();
        if (tid == 0) {
            unsigned gen = *(volatile unsigned*)&g_bar_gen;
            unsigned ticket = atomicAdd(&g_bar_count, 1u);
            if (ticket == NCTA - 1) {
                g_bar_count = 0;
                __threadfence();
                atomicAdd(&g_bar_gen, 1u);
            } else {
                while (*(volatile unsigned*)&g_bar_gen == gen) { }
            }
            __threadfence();
        }
        __syncthreads();
    }
}

// ---------------- final projection out = h_final @ W_out + b_out ------------
__global__ void __launch_bounds__(256) out_kernel(const float* __restrict__ Wout,
                                                  const float* __restrict__ bout,
                                                  float* __restrict__ out) {
    __shared__ float hs[HSZ];
    int b = blockIdx.x, n = threadIdx.x;
    for (int i = n; i < HSZ; i += 256) hs[i] = g_h[0][i * 64 + b];  // h^T
    __syncthreads();
    float acc = bout[n];
    #pragma unroll 8
    for (int k = 0; k < HSZ; k++) acc += hs[k] * Wout[k * OSZ + n];
    out[b * OSZ + n] = acc;
}

// ---------------- launch -----------------------------------------------------
extern "C" void kernel_launch(void* const* d_in, const int* in_sizes, int n_in,
                              void* d_out, int out_size) {
    const float* x    = (const float*)d_in[0];
    const float* Wf   = (const float*)d_in[1];
    const float* bf   = (const float*)d_in[2];
    const float* Wi   = (const float*)d_in[3];
    const float* bi   = (const float*)d_in[4];
    const float* Wc   = (const float*)d_in[5];
    const float* bc   = (const float*)d_in[6];
    const float* Wo   = (const float*)d_in[7];
    const float* bo   = (const float*)d_in[8];
    const float* Wout = (const float*)d_in[9];
    const float* bout = (const float*)d_in[10];
    float* out = (float*)d_out;

    cudaFuncSetAttribute(lstm_kernel, cudaFuncAttributeMaxDynamicSharedMemorySize,
                         SM_TOT * 4);

    prep_kernel<<<512, 256>>>(Wf, Wi, Wc, Wo, bf, bi, bc, bo);
    dim3 g(16, SEQ);
    xgemm_kernel<<<g, 256>>>(x);
    lstm_kernel<<<NCTA, TPB, SM_TOT * 4>>>();
    out_kernel<<<BATCH, 256>>>(Wout, bout, out);
}